// round 11
// baseline (speedup 1.0000x reference)
#include <cuda_runtime.h>
#include <cuda_fp16.h>
#include <cstdint>

#define N_NODES 100000
#define N_EDGES 1600000
#define IN_F    128
#define C1      32        // 2 heads * 16
#define NEG     0.2f
#define MAXDEG  64        // P(Binomial(1.6M,1e-5) > 64) ~ 1e-20 per node

// 4 cg-threads share each node (8-channel slices) => 256 nodes per 256-thread block
#define GEMM_BLOCKS ((N_NODES + 255) / 256)        // 391
#define SCAT_BLOCKS ((N_EDGES / 4 + 255) / 256)    // 1563

// ---------------- scratch (static __device__, no allocations) ----------------
// INVARIANT: g_deg is all-zero at kernel_launch entry (zero-init at load; agg2
// re-zeros it every call). This lets the scatter run with no prior zero pass.
__device__ uint4  g_h1[N_NODES * 4];        // layer-1 features fp16: 32 halves = 4 uint4/node
__device__ float  g_as1[N_NODES * 2];       // alpha_src per head (float2 layout)
__device__ float  g_ad1[N_NODES * 2];       // alpha_dst per head
__device__ int    g_deg[N_NODES];
__device__ int    g_nb[N_NODES * MAXDEG];   // padded adjacency buckets (src ids)
__device__ float  g_h2[N_NODES];            // layer-2 scalar feature per node

// ---------------- f32x2 helpers ----------------
__device__ __forceinline__ unsigned long long pk2(float a, float b) {
    unsigned long long r;
    asm("mov.b64 %0, {%1, %2};" : "=l"(r) : "f"(a), "f"(b));
    return r;
}
__device__ __forceinline__ void fma2(unsigned long long& d, unsigned long long a, unsigned long long b) {
    asm("fma.rn.f32x2 %0, %1, %2, %0;" : "+l"(d) : "l"(a), "l"(b));
}
__device__ __forceinline__ float2 unpk2(unsigned long long v) {
    float2 r;
    asm("mov.b64 {%0, %1}, %2;" : "=f"(r.x), "=f"(r.y) : "l"(v));
    return r;
}
__device__ __forceinline__ float lrelu(float x) { return x > 0.f ? x : NEG * x; }

// ---------------- K0: fused [GEMM role | scatter role] by blockIdx ----------------
// GEMM role: 4 nodes x 8 channels per thread, x loads register double-buffered
// so the ~250cyc L2 latency of iteration i+1's x overlaps iteration i's FMAs.
__global__ void __launch_bounds__(256) k_front(
    const float* __restrict__ x, const float* __restrict__ W1,
    const float* __restrict__ a_src, const float* __restrict__ a_dst,
    const int* __restrict__ ei)
{
    if (blockIdx.x >= GEMM_BLOCKS) {
        // ---- scatter role: bucket-CSR build, 4 edges/thread ----
        int e4 = (blockIdx.x - GEMM_BLOCKS) * 256 + threadIdx.x;
        if (e4 < N_EDGES / 4) {
            const int4* sv4 = reinterpret_cast<const int4*>(ei);
            int4 sv = sv4[e4];
            int4 dv = sv4[N_EDGES / 4 + e4];
            int ss[4] = {sv.x, sv.y, sv.z, sv.w};
            int dd[4] = {dv.x, dv.y, dv.z, dv.w};
#pragma unroll
            for (int j = 0; j < 4; j++) {
                int pos = atomicAdd(&g_deg[dd[j]], 1);
                if (pos < MAXDEG) g_nb[dd[j] * MAXDEG + pos] = ss[j];
            }
        }
        return;
    }

    // ---- GEMM role ----
    __shared__ __align__(16) float W1s[IN_F * C1];
    for (int i = threadIdx.x; i < IN_F * C1; i += 256) W1s[i] = W1[i];
    __syncthreads();

    int w    = (blockIdx.x * 256 + threadIdx.x) >> 5;   // global warp id
    int lane = threadIdx.x & 31;
    int ng   = lane >> 2, cg = lane & 3;                // cg: channel slice [8cg, 8cg+8)
    int n0   = w * 32 + ng * 4;                         // first node of this thread's quad
    if (n0 >= N_NODES) return;                          // warp-uniform (100000 % 32 == 0)

    // acc[j*4+p]: node j (0..3), channel pair p within slice (channels 8cg+2p, +1)
    unsigned long long acc[16];
#pragma unroll
    for (int i = 0; i < 16; i++) acc[i] = pk2(0.f, 0.f);

    const float4* xr0 = reinterpret_cast<const float4*>(x + (size_t)(n0 + 0) * IN_F);
    const float4* xr1 = reinterpret_cast<const float4*>(x + (size_t)(n0 + 1) * IN_F);
    const float4* xr2 = reinterpret_cast<const float4*>(x + (size_t)(n0 + 2) * IN_F);
    const float4* xr3 = reinterpret_cast<const float4*>(x + (size_t)(n0 + 3) * IN_F);

    // register double-buffer: issue iteration i+1's 4 LDGs before iteration i's FMAs
    float4 v0 = xr0[0], v1 = xr1[0], v2 = xr2[0], v3 = xr3[0];

    for (int c4 = 0; c4 < IN_F / 4; c4++) {
        float4 p0, p1, p2, p3;
        if (c4 + 1 < IN_F / 4) {
            p0 = xr0[c4 + 1]; p1 = xr1[c4 + 1]; p2 = xr2[c4 + 1]; p3 = xr3[c4 + 1];
        }
        float xA[4] = {v0.x, v0.y, v0.z, v0.w};
        float xB[4] = {v1.x, v1.y, v1.z, v1.w};
        float xC[4] = {v2.x, v2.y, v2.z, v2.w};
        float xD[4] = {v3.x, v3.y, v3.z, v3.w};
#pragma unroll
        for (int j = 0; j < 4; j++) {
            int k = c4 * 4 + j;
            const ulonglong2* wr = reinterpret_cast<const ulonglong2*>(&W1s[k * C1 + cg * 8]);
            ulonglong2 wa = wr[0], wb = wr[1];   // 4 f32x2 pairs = 8 channels
            unsigned long long xp;
            xp = pk2(xA[j], xA[j]);
            fma2(acc[0],  xp, wa.x); fma2(acc[1],  xp, wa.y);
            fma2(acc[2],  xp, wb.x); fma2(acc[3],  xp, wb.y);
            xp = pk2(xB[j], xB[j]);
            fma2(acc[4],  xp, wa.x); fma2(acc[5],  xp, wa.y);
            fma2(acc[6],  xp, wb.x); fma2(acc[7],  xp, wb.y);
            xp = pk2(xC[j], xC[j]);
            fma2(acc[8],  xp, wa.x); fma2(acc[9],  xp, wa.y);
            fma2(acc[10], xp, wb.x); fma2(acc[11], xp, wb.y);
            xp = pk2(xD[j], xD[j]);
            fma2(acc[12], xp, wa.x); fma2(acc[13], xp, wa.y);
            fma2(acc[14], xp, wb.x); fma2(acc[15], xp, wb.y);
        }
        v0 = p0; v1 = p1; v2 = p2; v3 = p3;
    }

    // h1 store: node j's 8-channel slice as 8 fp16 = one uint4 at row offset cg
#pragma unroll
    for (int j = 0; j < 4; j++) {
        uint32_t hp[4];
#pragma unroll
        for (int p = 0; p < 4; p++) {
            float2 f = unpk2(acc[j * 4 + p]);
            __half2 h = __floats2half2_rn(f.x, f.y);
            hp[p] = *reinterpret_cast<uint32_t*>(&h);
        }
        g_h1[(n0 + j) * 4 + cg] = make_uint4(hp[0], hp[1], hp[2], hp[3]);
    }

    // alpha partials over this thread's 8 channels; a_src/a_dst flat [2,16] ==
    // channel order, so slice = [8cg, 8cg+8)
    ulonglong2 sA = *reinterpret_cast<const ulonglong2*>(a_src + cg * 8);
    ulonglong2 sB = *reinterpret_cast<const ulonglong2*>(a_src + cg * 8 + 4);
    ulonglong2 dA = *reinterpret_cast<const ulonglong2*>(a_dst + cg * 8);
    ulonglong2 dB = *reinterpret_cast<const ulonglong2*>(a_dst + cg * 8 + 4);
#pragma unroll
    for (int j = 0; j < 4; j++) {
        unsigned long long ps = pk2(0.f, 0.f), pd = pk2(0.f, 0.f);
        fma2(ps, acc[j * 4 + 0], sA.x); fma2(ps, acc[j * 4 + 1], sA.y);
        fma2(ps, acc[j * 4 + 2], sB.x); fma2(ps, acc[j * 4 + 3], sB.y);
        fma2(pd, acc[j * 4 + 0], dA.x); fma2(pd, acc[j * 4 + 1], dA.y);
        fma2(pd, acc[j * 4 + 2], dB.x); fma2(pd, acc[j * 4 + 3], dB.y);
        float2 f;
        f = unpk2(ps); float vs = f.x + f.y;
        f = unpk2(pd); float vd = f.x + f.y;
        // combine the cg-pair halves of each head (cg0+cg1 -> head0, cg2+cg3 -> head1)
        vs += __shfl_xor_sync(0xffffffffu, vs, 1);
        vd += __shfl_xor_sync(0xffffffffu, vd, 1);
        if ((cg & 1) == 0) {
            int n = n0 + j, hd = cg >> 1;
            g_as1[2 * n + hd] = vs;
            g_ad1[2 * n + hd] = vd;
        }
    }
}

// ---------------- K1: layer-1 softmax-aggregate (warp/node), fully pipelined ----------------
// lane = slot*8 + q : slot 0..3 (edge in group of 4), q 0..7 (channel quad), head = q>>2
// Pipelines BOTH the nb index and the dependent as1/h1 gathers one group ahead.
__global__ void __launch_bounds__(256) k_agg1(
    const float* __restrict__ b1, const float* __restrict__ W2)
{
    int wg = (blockIdx.x * 256 + threadIdx.x) >> 5;
    if (wg >= N_NODES) return;
    int d = wg;
    int lane = threadIdx.x & 31;
    int slot = lane >> 3, q = lane & 7, hd = q >> 2;

    int base = d * MAXDEG;
    int deg  = g_deg[d];
    if (deg > MAXDEG) deg = MAXDEG;

    float2 adv = *reinterpret_cast<const float2*>(&g_ad1[2 * d]);
    float  adh = hd ? adv.y : adv.x;

    const uint2* h1q = reinterpret_cast<const uint2*>(g_h1);  // 8 uint2 per node row

    float4 acc = make_float4(0.f, 0.f, 0.f, 0.f);
    float den = 0.f;

    // self-loop (slot 0 only)
    if (slot == 0) {
        float2 asd = *reinterpret_cast<const float2*>(&g_as1[2 * d]);
        float w = __expf(lrelu((hd ? asd.y : asd.x) + adh));
        uint2 hv0 = h1q[d * 8 + q];
        float2 f0 = __half22float2(*reinterpret_cast<const __half2*>(&hv0.x));
        float2 f1 = __half22float2(*reinterpret_cast<const __half2*>(&hv0.y));
        acc.x = w * f0.x; acc.y = w * f0.y; acc.z = w * f1.x; acc.w = w * f1.y;
        den = w;
    }

    // software pipeline: (s, asv, hv) loaded one 4-edge group ahead
    int s = (slot < deg) ? g_nb[base + slot] : -1;
    float2 asv = make_float2(0.f, 0.f);
    uint2  hv  = make_uint2(0u, 0u);
    if (s >= 0) {
        asv = *reinterpret_cast<const float2*>(&g_as1[2 * s]);
        hv  = h1q[s * 8 + q];
    }

    for (int i = 0; i < deg; i += 4) {
        int jn = i + 4 + slot;
        int sn = (jn < deg) ? g_nb[base + jn] : -1;
        float2 asvn = make_float2(0.f, 0.f);
        uint2  hvn  = make_uint2(0u, 0u);
        if (sn >= 0) {
            asvn = *reinterpret_cast<const float2*>(&g_as1[2 * sn]);
            hvn  = h1q[sn * 8 + q];
        }
        if (s >= 0) {
            float w = __expf(lrelu((hd ? asv.y : asv.x) + adh));
            float2 f0 = __half22float2(*reinterpret_cast<const __half2*>(&hv.x));
            float2 f1 = __half22float2(*reinterpret_cast<const __half2*>(&hv.y));
            acc.x += w * f0.x; acc.y += w * f0.y; acc.z += w * f1.x; acc.w += w * f1.y;
            den += w;
        }
        s = sn; asv = asvn; hv = hvn;
    }

    // reduce over the 4 slots (lanes l, l^8, l^16, l^24 share q)
#pragma unroll
    for (int off = 8; off <= 16; off <<= 1) {
        acc.x += __shfl_xor_sync(0xffffffffu, acc.x, off);
        acc.y += __shfl_xor_sync(0xffffffffu, acc.y, off);
        acc.z += __shfl_xor_sync(0xffffffffu, acc.z, off);
        acc.w += __shfl_xor_sync(0xffffffffu, acc.w, off);
        den   += __shfl_xor_sync(0xffffffffu, den,   off);
    }

    float inv = 1.f / (den + 1e-16f);
    float4 bv  = *reinterpret_cast<const float4*>(&b1[q * 4]);
    float o0 = acc.x * inv + bv.x;
    float o1 = acc.y * inv + bv.y;
    float o2 = acc.z * inv + bv.z;
    float o3 = acc.w * inv + bv.w;
    o0 = o0 > 0.f ? o0 : expm1f(o0);
    o1 = o1 > 0.f ? o1 : expm1f(o1);
    o2 = o2 > 0.f ? o2 : expm1f(o2);
    o3 = o3 > 0.f ? o3 : expm1f(o3);

    // fused layer-2 projection: h2[d] = sum_c elu_out[c] * W2[c]
    float4 wq = *reinterpret_cast<const float4*>(&W2[q * 4]);
    float p = o0 * wq.x + o1 * wq.y + o2 * wq.z + o3 * wq.w;
#pragma unroll
    for (int off = 1; off <= 4; off <<= 1) p += __shfl_xor_sync(0xffffffffu, p, off);

    if (lane == 0) g_h2[d] = p;
}

// ---------------- K2: layer-2 softmax-aggregate (4 lanes/node) + g_deg re-zero ----------------
__global__ void __launch_bounds__(256) k_agg2(
    const float* __restrict__ a_src2, const float* __restrict__ a_dst2,
    const float* __restrict__ b2, float* __restrict__ out)
{
    int t = blockIdx.x * 256 + threadIdx.x;
    int d = t >> 2;          // 4 lanes per node
    int q = t & 3;
    if (d >= N_NODES) return;

    float a_s = a_src2[0];
    float a_d = a_dst2[0];
    float h2d = g_h2[d];
    float addv = a_d * h2d;

    int base = d * MAXDEG;   // 16B-aligned buckets
    int deg  = g_deg[d];
    if (deg > MAXDEG) deg = MAXDEG;

    float num = 0.f, den = 0.f;
    if (q == 0) {  // self loop
        float w = __expf(lrelu(a_s * h2d + addv));
        num = w * h2d; den = w;
    }

    // lane q covers edges [16*chunk + 4q, +4): int4 nb load, 4-way gather MLP
    for (int c = 4 * q; c < deg; c += 16) {
        int4 v = *reinterpret_cast<const int4*>(&g_nb[base + c]);
        if (c + 0 < deg) { float h = g_h2[v.x]; float w = __expf(lrelu(a_s * h + addv)); num += w * h; den += w; }
        if (c + 1 < deg) { float h = g_h2[v.y]; float w = __expf(lrelu(a_s * h + addv)); num += w * h; den += w; }
        if (c + 2 < deg) { float h = g_h2[v.z]; float w = __expf(lrelu(a_s * h + addv)); num += w * h; den += w; }
        if (c + 3 < deg) { float h = g_h2[v.w]; float w = __expf(lrelu(a_s * h + addv)); num += w * h; den += w; }
    }

    // reduce across the 4 lanes of this node
#pragma unroll
    for (int off = 1; off <= 2; off <<= 1) {
        num += __shfl_xor_sync(0xffffffffu, num, off);
        den += __shfl_xor_sync(0xffffffffu, den, off);
    }

    if (q == 0) {
        out[d] = num / (den + 1e-16f) + b2[0];
        g_deg[d] = 0;   // restore the deg==0 invariant for the next call
    }
}

// ---------------- launch ----------------
extern "C" void kernel_launch(void* const* d_in, const int* in_sizes, int n_in,
                              void* d_out, int out_size)
{
    const float* x    = (const float*)d_in[0];
    const int*   ei   = (const int*)  d_in[1];
    const float* W1   = (const float*)d_in[2];
    const float* as1  = (const float*)d_in[3];
    const float* ad1  = (const float*)d_in[4];
    const float* b1   = (const float*)d_in[5];
    const float* W2   = (const float*)d_in[6];
    const float* as2  = (const float*)d_in[7];
    const float* ad2  = (const float*)d_in[8];
    const float* b2   = (const float*)d_in[9];
    float* out = (float*)d_out;

    k_front<<<GEMM_BLOCKS + SCAT_BLOCKS, 256>>>(x, W1, as1, ad1, ei);
    k_agg1<<<(N_NODES * 32 + 255) / 256, 256>>>(b1, W2);
    k_agg2<<<(N_NODES * 4 + 255) / 256, 256>>>(as2, ad2, b2, out);
}